// round 3
// baseline (speedup 1.0000x reference)
#include <cuda_runtime.h>
#include <cuda_bf16.h>

// ---------------- problem constants ----------------
#define MAXN 100000
#define MAXE 1200000
#define DIN  64
#define DHID 64
#define DOUT 34

// ---------------- scratch (device globals; referenced ONLY from device code) ----------------
__device__ float g_xw [(size_t)MAXN * 64];     // x@W1   (layer 1 pre-aggregation)
__device__ float g_h  [(size_t)MAXN * 64];     // post-softmax hidden
__device__ float g_xw2[(size_t)MAXN * DOUT];   // h@W2   (layer 2 pre-aggregation, stride 34)
__device__ float g_dinv[MAXN];
__device__ int   g_indeg[MAXN];
__device__ int   g_cnt[MAXN];
__device__ int   g_rowstart[MAXN + 1];
__device__ int   g_bsum[128];
__device__ int   g_csr_src[MAXE];
__device__ float g_csr_norm[MAXE];

// ---------------- preprocessing ----------------
__global__ void k_init(int n) {
    int i = blockIdx.x * blockDim.x + threadIdx.x;
    if (i < n) { g_indeg[i] = 0; g_cnt[i] = 0; }
}

__global__ void k_count(const int* __restrict__ dst, int e) {
    int i = blockIdx.x * blockDim.x + threadIdx.x;
    if (i < e) atomicAdd(&g_indeg[dst[i]], 1);
}

__global__ void k_dinv(int n) {
    int i = blockIdx.x * blockDim.x + threadIdx.x;
    if (i < n) g_dinv[i] = rsqrtf((float)(g_indeg[i] + 1));   // +1 self-loop
}

// exclusive scan of g_indeg -> g_rowstart  (3 kernels, 1024-wide blocks)
__global__ void k_scan_local(int n) {
    __shared__ int wsum[32];
    int tid = threadIdx.x, lane = tid & 31, wid = tid >> 5;
    int gid = blockIdx.x * 1024 + tid;
    int v = (gid < n) ? g_indeg[gid] : 0;
    int x = v;
    #pragma unroll
    for (int o = 1; o < 32; o <<= 1) {
        int y = __shfl_up_sync(0xffffffffu, x, o);
        if (lane >= o) x += y;
    }
    if (lane == 31) wsum[wid] = x;
    __syncthreads();
    if (wid == 0) {
        int w = wsum[lane];
        int xx = w;
        #pragma unroll
        for (int o = 1; o < 32; o <<= 1) {
            int y = __shfl_up_sync(0xffffffffu, xx, o);
            if (lane >= o) xx += y;
        }
        wsum[lane] = xx - w;                      // exclusive warp offsets
        if (lane == 31) g_bsum[blockIdx.x] = xx;  // block total
    }
    __syncthreads();
    if (gid < n) g_rowstart[gid] = (x - v) + wsum[wid];
}

__global__ void k_scan_bsum(int nb) {
    __shared__ int s[128];
    int t = threadIdx.x;
    int orig = (t < nb) ? g_bsum[t] : 0;
    s[t] = orig;
    __syncthreads();
    for (int o = 1; o < 128; o <<= 1) {
        int v = (t >= o) ? s[t - o] : 0;
        __syncthreads();
        s[t] += v;
        __syncthreads();
    }
    if (t < nb) g_bsum[t] = s[t] - orig;          // exclusive
}

__global__ void k_scan_add(int n, int etot) {
    int gid = blockIdx.x * 1024 + threadIdx.x;
    if (gid < n) g_rowstart[gid] += g_bsum[blockIdx.x];
    if (gid == 0) g_rowstart[n] = etot;
}

__global__ void k_place(const int* __restrict__ src, const int* __restrict__ dst, int e) {
    int i = blockIdx.x * blockDim.x + threadIdx.x;
    if (i >= e) return;
    int d = dst[i], s = src[i];
    int pos = g_rowstart[d] + atomicAdd(&g_cnt[d], 1);
    g_csr_src[pos]  = s;
    g_csr_norm[pos] = g_dinv[s] * g_dinv[d];
}

// ---------------- dense GEMMs (thread-per-row, W in smem; outputs are device globals) ----------------
__global__ __launch_bounds__(256) void k_gemm64(const float* __restrict__ x,
                                                const float* __restrict__ W, int n) {
    __shared__ float Ws[64 * 64];
    for (int i = threadIdx.x; i < 64 * 64; i += 256) Ws[i] = W[i];
    __syncthreads();
    int row = blockIdx.x * 256 + threadIdx.x;
    if (row >= n) return;
    float acc[64];
    #pragma unroll
    for (int j = 0; j < 64; j++) acc[j] = 0.f;
    const float4* xr = reinterpret_cast<const float4*>(x + (size_t)row * 64);
    #pragma unroll 2
    for (int k4 = 0; k4 < 16; k4++) {
        float4 xv = xr[k4];
        int k = k4 * 4;
        #pragma unroll
        for (int j = 0; j < 64; j++) {
            acc[j] = fmaf(xv.x, Ws[(k + 0) * 64 + j], acc[j]);
            acc[j] = fmaf(xv.y, Ws[(k + 1) * 64 + j], acc[j]);
            acc[j] = fmaf(xv.z, Ws[(k + 2) * 64 + j], acc[j]);
            acc[j] = fmaf(xv.w, Ws[(k + 3) * 64 + j], acc[j]);
        }
    }
    float4* o = reinterpret_cast<float4*>(g_xw + (size_t)row * 64);
    #pragma unroll
    for (int j = 0; j < 16; j++)
        o[j] = make_float4(acc[4 * j], acc[4 * j + 1], acc[4 * j + 2], acc[4 * j + 3]);
}

__global__ __launch_bounds__(256) void k_gemm34(const float* __restrict__ W, int n) {
    __shared__ float Ws[64 * DOUT];
    for (int i = threadIdx.x; i < 64 * DOUT; i += 256) Ws[i] = W[i];
    __syncthreads();
    int row = blockIdx.x * 256 + threadIdx.x;
    if (row >= n) return;
    float acc[DOUT];
    #pragma unroll
    for (int j = 0; j < DOUT; j++) acc[j] = 0.f;
    const float4* xr = reinterpret_cast<const float4*>(g_h + (size_t)row * 64);
    #pragma unroll 2
    for (int k4 = 0; k4 < 16; k4++) {
        float4 xv = xr[k4];
        int k = k4 * 4;
        #pragma unroll
        for (int j = 0; j < DOUT; j++) {
            acc[j] = fmaf(xv.x, Ws[(k + 0) * DOUT + j], acc[j]);
            acc[j] = fmaf(xv.y, Ws[(k + 1) * DOUT + j], acc[j]);
            acc[j] = fmaf(xv.z, Ws[(k + 2) * DOUT + j], acc[j]);
            acc[j] = fmaf(xv.w, Ws[(k + 3) * DOUT + j], acc[j]);
        }
    }
    float2* o = reinterpret_cast<float2*>(g_xw2 + (size_t)row * DOUT);
    #pragma unroll
    for (int j = 0; j < DOUT / 2; j++) o[j] = make_float2(acc[2 * j], acc[2 * j + 1]);
}

// ---------------- aggregation layer 1 (+bias, relu, softmax) : one warp per node ----------------
__global__ __launch_bounds__(256) void k_agg1(const float* __restrict__ b1, int n) {
    int warp = (blockIdx.x * 256 + threadIdx.x) >> 5;
    int lane = threadIdx.x & 31;
    if (warp >= n) return;
    int i = warp;
    float di = g_dinv[i];
    float selfw = di * di;
    float a0 = selfw * g_xw[(size_t)i * 64 + lane];
    float a1 = selfw * g_xw[(size_t)i * 64 + lane + 32];
    int e0i = g_rowstart[i], e1i = g_rowstart[i + 1];
    for (int e = e0i; e < e1i; e++) {
        int   s  = g_csr_src[e];
        float nm = g_csr_norm[e];
        a0 = fmaf(nm, g_xw[(size_t)s * 64 + lane],      a0);
        a1 = fmaf(nm, g_xw[(size_t)s * 64 + lane + 32], a1);
    }
    a0 += b1[lane]; a1 += b1[lane + 32];
    a0 = fmaxf(a0, 0.f); a1 = fmaxf(a1, 0.f);
    // softmax over 64 cols (2 per lane)
    float m = fmaxf(a0, a1);
    #pragma unroll
    for (int o = 16; o > 0; o >>= 1) m = fmaxf(m, __shfl_xor_sync(0xffffffffu, m, o));
    float ex0 = __expf(a0 - m), ex1 = __expf(a1 - m);
    float sum = ex0 + ex1;
    #pragma unroll
    for (int o = 16; o > 0; o >>= 1) sum += __shfl_xor_sync(0xffffffffu, sum, o);
    float inv = __frcp_rn(sum);
    g_h[(size_t)i * 64 + lane]      = ex0 * inv;
    g_h[(size_t)i * 64 + lane + 32] = ex1 * inv;
}

// ---------------- aggregation layer 2 (+bias) : one warp per node ----------------
__global__ __launch_bounds__(256) void k_agg2(const float* __restrict__ b2,
                                              float* __restrict__ out, int n) {
    int warp = (blockIdx.x * 256 + threadIdx.x) >> 5;
    int lane = threadIdx.x & 31;
    if (warp >= n) return;
    int i = warp;
    float di = g_dinv[i];
    float selfw = di * di;
    int c1 = lane + 32;
    float a0 = selfw * g_xw2[(size_t)i * DOUT + lane];
    float a1 = (c1 < DOUT) ? selfw * g_xw2[(size_t)i * DOUT + c1] : 0.f;
    int e0i = g_rowstart[i], e1i = g_rowstart[i + 1];
    for (int e = e0i; e < e1i; e++) {
        int   s  = g_csr_src[e];
        float nm = g_csr_norm[e];
        a0 = fmaf(nm, g_xw2[(size_t)s * DOUT + lane], a0);
        if (c1 < DOUT) a1 = fmaf(nm, g_xw2[(size_t)s * DOUT + c1], a1);
    }
    out[(size_t)i * DOUT + lane] = a0 + b2[lane];
    if (c1 < DOUT) out[(size_t)i * DOUT + c1] = a1 + b2[c1];
}

// ---------------- launch ----------------
extern "C" void kernel_launch(void* const* d_in, const int* in_sizes, int n_in,
                              void* d_out, int out_size) {
    const float* x   = (const float*)d_in[0];
    const int*   ei  = (const int*)  d_in[1];
    const float* W1  = (const float*)d_in[2];
    const float* b1  = (const float*)d_in[3];
    const float* W2  = (const float*)d_in[4];
    const float* b2  = (const float*)d_in[5];
    float* out = (float*)d_out;

    int n = in_sizes[0] / DIN;         // 100000
    int e = in_sizes[1] / 2;           // 1200000
    const int* src = ei;
    const int* dst = ei + e;

    int nb_n   = (n + 255) / 256;
    int nb_e   = (e + 255) / 256;
    int nb_s   = (n + 1023) / 1024;    // scan blocks (<=128)
    int nb_agg = (n * 32 + 255) / 256;

    k_init<<<nb_n, 256>>>(n);
    k_count<<<nb_e, 256>>>(dst, e);
    k_dinv<<<nb_n, 256>>>(n);
    k_scan_local<<<nb_s, 1024>>>(n);
    k_scan_bsum<<<1, 128>>>(nb_s);
    k_scan_add<<<nb_s, 1024>>>(n, e);
    k_place<<<nb_e, 256>>>(src, dst, e);

    k_gemm64<<<(n + 255) / 256, 256>>>(x, W1, n);
    k_agg1<<<nb_agg, 256>>>(b1, n);
    k_gemm34<<<(n + 255) / 256, 256>>>(W2, n);
    k_agg2<<<nb_agg, 256>>>(b2, out, n);
}